// round 6
// baseline (speedup 1.0000x reference)
#include <cuda_runtime.h>

// FourierConv2D via DFT-as-GEMM + Hermitian half-plane symmetry, fp32x2 packed math.
//   All complex data stored interleaved (float2). Complex MAC = 2x fma.rn.f32x2
//   (SASS FFMA2, 2 FMA/issue-slot) instead of 4x 3-reg FFMA (1 FMA/slot).
//   acc{cr,ci} += {ar,ar}*{br,bi} + {ai,ai}*{-bi,br}
// kx padded 511->512 (pad zero) so every GEMM is tile-exact and 16B-aligned.
// R6 fix: float4* tile-loader pointers advance 8 float4 (=16 complex) per k-step.

namespace {
constexpr int N5    = 511;
constexpr int HH    = 256;
constexpr int NP    = 512;
constexpr int NB    = 4;
constexpr int NCIN  = 4;
constexpr int NCOUT = 8;
constexpr int PLANE = N5 * N5;
constexpr int HALFP = HH * NP;
constexpr int SQ    = HH * HH;
constexpr int BC    = NB * NCIN;     // 16
constexpr int BO    = NB * NCOUT;    // 32
}

using u64 = unsigned long long;

__device__ __forceinline__ void fma2(u64 &d, u64 a, u64 b) {
    asm("fma.rn.f32x2 %0, %1, %2, %0;" : "+l"(d) : "l"(a), "l"(b));
}
__device__ __forceinline__ u64 pk2(float x, float y) {
    u64 r; asm("mov.b64 %0, {%1, %2};" : "=l"(r) : "f"(x), "f"(y)); return r;
}
__device__ __forceinline__ float2 upk(u64 v) {
    float2 f; asm("mov.b64 {%0, %1}, %2;" : "=f"(f.x), "=f"(f.y) : "l"(v)); return f;
}

// ---- scratch (device globals; interleaved complex) ----
__device__ float2 g_A[NP*HH];     // A[kx][n] = exp(-2pi i kx n/511); row 511 = 0
__device__ float2 g_E[HH*NP];     // Ec[x][kx] = exp(+2pi i kx (x+127)/511)/511; col 511 = 0
__device__ float2 g_E5[HH*HH];    // E5[y][ky] = w(ky) exp(+2pi i ky (y+127)/511); w=1/511 (ky=0) else 2/511
__device__ float2 g_T1[BC*SQ];
__device__ float2 g_F[BC*HALFP];
__device__ float2 g_G[BO*HALFP];
__device__ float2 g_T2[BO*SQ];

// ---- twiddle init ----
__global__ void k_twiddle() {
    const int idx = blockIdx.x * blockDim.x + threadIdx.x;   // 0..131071
    const float TWO_PI = 6.283185307179586f;
    {   const int k = idx >> 8, n = idx & 255;               // A: [kx][n]
        if (k == N5) g_A[idx] = make_float2(0.f, 0.f);
        else {
            int m = (k * n) % N5;
            float s, c; sincosf(TWO_PI * (float)m / (float)N5, &s, &c);
            g_A[idx] = make_float2(c, -s);
        }
    }
    {   const int x = idx >> 9, k = idx & 511;               // Ec: [x][kx]
        if (k == N5) g_E[idx] = make_float2(0.f, 0.f);
        else {
            int m = (k * (x + 127)) % N5;
            float s, c; sincosf(TWO_PI * (float)m / (float)N5, &s, &c);
            const float inv = 1.0f / (float)N5;
            g_E[idx] = make_float2(c * inv, s * inv);
        }
    }
    if (idx < HH * HH) {
        const int y = idx / HH, ky = idx - y * HH;
        int m = (ky * (y + 127)) % N5;
        float s, c; sincosf(TWO_PI * (float)m / (float)N5, &s, &c);
        const float w = (ky == 0) ? (1.0f / (float)N5) : (2.0f / (float)N5);
        g_E5[idx] = make_float2(c * w, s * w);
    }
}

// ---- stage 1: T1[z] (256x256 c) = A[0:256] @ X[z] (real) ----
// acc{cr,ci} += {ar,ai} * {b,b}
__global__ void __launch_bounds__(128, 4) k_stage1(const float* __restrict__ im) {
    const int z = blockIdx.z;
    const float* __restrict__ X = im + (size_t)z * SQ;
    float2* __restrict__ C = g_T1 + (size_t)z * SQ;

    __shared__ u64 As[16][66];      // native {ar,ai}
    __shared__ u64 Bs[16][66];      // dup {b,b}
    const int tid = threadIdx.x;
    const int tx = tid & 15, ty = tid >> 4;
    const int m0 = blockIdx.y * 64, n0 = blockIdx.x * 64;
    const int rw = tid >> 1, k8 = (tid & 1) * 8;
    const int kb0 = (tid >> 4) * 2, nb = (tid & 15) * 4;

    const float4* pA = reinterpret_cast<const float4*>(g_A + (size_t)(m0 + rw)*HH + k8);

    u64 acc[8][4] = {};

    for (int k0 = 0; k0 < HH; k0 += 16) {
        float4 a0 = pA[0], a1 = pA[1], a2 = pA[2], a3 = pA[3];  pA += 8;  // 16 complex
        As[k8+0][rw] = pk2(a0.x, a0.y);  As[k8+1][rw] = pk2(a0.z, a0.w);
        As[k8+2][rw] = pk2(a1.x, a1.y);  As[k8+3][rw] = pk2(a1.z, a1.w);
        As[k8+4][rw] = pk2(a2.x, a2.y);  As[k8+5][rw] = pk2(a2.z, a2.w);
        As[k8+6][rw] = pk2(a3.x, a3.y);  As[k8+7][rw] = pk2(a3.z, a3.w);
        float4 b0 = *reinterpret_cast<const float4*>(X + (size_t)(k0 + kb0)*HH + n0 + nb);
        float4 b1 = *reinterpret_cast<const float4*>(X + (size_t)(k0 + kb0 + 1)*HH + n0 + nb);
        Bs[kb0][nb+0] = pk2(b0.x, b0.x);  Bs[kb0][nb+1] = pk2(b0.y, b0.y);
        Bs[kb0][nb+2] = pk2(b0.z, b0.z);  Bs[kb0][nb+3] = pk2(b0.w, b0.w);
        Bs[kb0+1][nb+0] = pk2(b1.x, b1.x);  Bs[kb0+1][nb+1] = pk2(b1.y, b1.y);
        Bs[kb0+1][nb+2] = pk2(b1.z, b1.z);  Bs[kb0+1][nb+3] = pk2(b1.w, b1.w);
        __syncthreads();

        #pragma unroll 4
        for (int k = 0; k < 16; k++) {
            const u64* pa = &As[k][ty*8];
            u64 av[8];
            #pragma unroll
            for (int i = 0; i < 8; i++) av[i] = pa[i];
            const float4* pb = reinterpret_cast<const float4*>(&Bs[k][tx*4]);
            float4 q0 = pb[0], q1 = pb[1];
            u64 bv[4] = { pk2(q0.x, q0.y), pk2(q0.z, q0.w),
                          pk2(q1.x, q1.y), pk2(q1.z, q1.w) };
            #pragma unroll
            for (int i = 0; i < 8; i++)
                #pragma unroll
                for (int j = 0; j < 4; j++)
                    fma2(acc[i][j], av[i], bv[j]);
        }
        __syncthreads();
    }
    #pragma unroll
    for (int i = 0; i < 8; i++) {
        const int gm = m0 + ty*8 + i;
        float2 c0 = upk(acc[i][0]), c1 = upk(acc[i][1]);
        float2 c2 = upk(acc[i][2]), c3 = upk(acc[i][3]);
        float4* pc = reinterpret_cast<float4*>(C + (size_t)gm*HH + n0 + tx*4);
        pc[0] = make_float4(c0.x, c0.y, c1.x, c1.y);
        pc[1] = make_float4(c2.x, c2.y, c3.x, c3.y);
    }
}

// ---- complex GEMM, B transposed: C(256 x N_) = A(256 x K_) @ B(N_ x K_)^T ----
template<int N_, int K_>
__device__ __forceinline__ void cgemm2_bt(
    const float2* __restrict__ Ag, const float2* __restrict__ Bg,
    float2* __restrict__ C)
{
    __shared__ u64 Ap[16][66], Aq[16][66];   // {ar,ar}, {ai,ai}
    __shared__ u64 Bp[16][66], Bq[16][66];   // {br,bi}, {-bi,br}
    const int tid = threadIdx.x;
    const int tx = tid & 15, ty = tid >> 4;
    const int m0 = blockIdx.y * 64, n0 = blockIdx.x * 64;
    const int rw = tid >> 1, k8 = (tid & 1) * 8;

    const float4* pA = reinterpret_cast<const float4*>(Ag + (size_t)(m0 + rw)*K_ + k8);
    const float4* pB = reinterpret_cast<const float4*>(Bg + (size_t)(n0 + rw)*K_ + k8);

    u64 acc[8][4] = {};

    for (int k0 = 0; k0 < K_; k0 += 16) {
        float4 a0 = pA[0], a1 = pA[1], a2 = pA[2], a3 = pA[3];  pA += 8;  // 16 complex
        float4 b0 = pB[0], b1 = pB[1], b2 = pB[2], b3 = pB[3];  pB += 8;
        Ap[k8+0][rw] = pk2(a0.x, a0.x);  Aq[k8+0][rw] = pk2(a0.y, a0.y);
        Ap[k8+1][rw] = pk2(a0.z, a0.z);  Aq[k8+1][rw] = pk2(a0.w, a0.w);
        Ap[k8+2][rw] = pk2(a1.x, a1.x);  Aq[k8+2][rw] = pk2(a1.y, a1.y);
        Ap[k8+3][rw] = pk2(a1.z, a1.z);  Aq[k8+3][rw] = pk2(a1.w, a1.w);
        Ap[k8+4][rw] = pk2(a2.x, a2.x);  Aq[k8+4][rw] = pk2(a2.y, a2.y);
        Ap[k8+5][rw] = pk2(a2.z, a2.z);  Aq[k8+5][rw] = pk2(a2.w, a2.w);
        Ap[k8+6][rw] = pk2(a3.x, a3.x);  Aq[k8+6][rw] = pk2(a3.y, a3.y);
        Ap[k8+7][rw] = pk2(a3.z, a3.z);  Aq[k8+7][rw] = pk2(a3.w, a3.w);
        Bp[k8+0][rw] = pk2(b0.x, b0.y);  Bq[k8+0][rw] = pk2(-b0.y, b0.x);
        Bp[k8+1][rw] = pk2(b0.z, b0.w);  Bq[k8+1][rw] = pk2(-b0.w, b0.z);
        Bp[k8+2][rw] = pk2(b1.x, b1.y);  Bq[k8+2][rw] = pk2(-b1.y, b1.x);
        Bp[k8+3][rw] = pk2(b1.z, b1.w);  Bq[k8+3][rw] = pk2(-b1.w, b1.z);
        Bp[k8+4][rw] = pk2(b2.x, b2.y);  Bq[k8+4][rw] = pk2(-b2.y, b2.x);
        Bp[k8+5][rw] = pk2(b2.z, b2.w);  Bq[k8+5][rw] = pk2(-b2.w, b2.z);
        Bp[k8+6][rw] = pk2(b3.x, b3.y);  Bq[k8+6][rw] = pk2(-b3.y, b3.x);
        Bp[k8+7][rw] = pk2(b3.z, b3.w);  Bq[k8+7][rw] = pk2(-b3.w, b3.z);
        __syncthreads();

        #pragma unroll 4
        for (int k = 0; k < 16; k++) {
            const u64* pap = &Ap[k][ty*8];
            const u64* paq = &Aq[k][ty*8];
            u64 ar[8], ai[8];
            #pragma unroll
            for (int i = 0; i < 8; i++) { ar[i] = pap[i]; ai[i] = paq[i]; }
            const float4* pbp = reinterpret_cast<const float4*>(&Bp[k][tx*4]);
            const float4* pbq = reinterpret_cast<const float4*>(&Bq[k][tx*4]);
            float4 p0 = pbp[0], p1 = pbp[1];
            float4 q0 = pbq[0], q1 = pbq[1];
            u64 bp[4] = { pk2(p0.x, p0.y), pk2(p0.z, p0.w),
                          pk2(p1.x, p1.y), pk2(p1.z, p1.w) };
            u64 bq[4] = { pk2(q0.x, q0.y), pk2(q0.z, q0.w),
                          pk2(q1.x, q1.y), pk2(q1.z, q1.w) };
            #pragma unroll
            for (int i = 0; i < 8; i++)
                #pragma unroll
                for (int j = 0; j < 4; j++) {
                    fma2(acc[i][j], ar[i], bp[j]);
                    fma2(acc[i][j], ai[i], bq[j]);
                }
        }
        __syncthreads();
    }
    #pragma unroll
    for (int i = 0; i < 8; i++) {
        const int gm = m0 + ty*8 + i;
        float2 c0 = upk(acc[i][0]), c1 = upk(acc[i][1]);
        float2 c2 = upk(acc[i][2]), c3 = upk(acc[i][3]);
        float4* pc = reinterpret_cast<float4*>(C + (size_t)gm*N_ + n0 + tx*4);
        pc[0] = make_float4(c0.x, c0.y, c1.x, c1.y);
        pc[1] = make_float4(c2.x, c2.y, c3.x, c3.y);
    }
}

// stage 2: F[z] (256x512) = T1[z] (256x256) @ g_A(512x256)^T
__global__ void __launch_bounds__(128, 4) k_stage2() {
    const int z = blockIdx.z;
    cgemm2_bt<NP, HH>(g_T1 + (size_t)z*SQ, g_A, g_F + (size_t)z*HALFP);
}

// stage 4: T2[z] (256x256) = G[z] (256x512) @ g_E(256x512)^T
__global__ void __launch_bounds__(128, 4) k_stage4() {
    const int z = blockIdx.z;
    cgemm2_bt<HH, NP>(g_G + (size_t)z*HALFP, g_E, g_T2 + (size_t)z*SQ);
}

// ---- stage 3: half-plane pointwise multiply by Hermitian part of W + cin sum ----
__global__ void k_pointwise(const float* __restrict__ w) {
    const int p = blockIdx.x * blockDim.x + threadIdx.x;  // ky*512+kx
    const int o = blockIdx.y;
    const int ky = p >> 9, kx = p & 511;
    if (kx == N5) {
        #pragma unroll
        for (int b = 0; b < NB; b++)
            g_G[(size_t)(b*NCOUT + o)*HALFP + p] = make_float2(0.f, 0.f);
        return;
    }
    const int ky2 = (N5 - ky) % N5;
    const int kx2 = (N5 - kx) % N5;
    const size_t pw = (size_t)ky * N5 + kx;
    const size_t pm = (size_t)ky2 * N5 + kx2;

    float2 w1v[NCIN], w2v[NCIN];
    #pragma unroll
    for (int c = 0; c < NCIN; c++) {
        const float* wb = w + (size_t)(o*NCIN + c) * PLANE * 2;
        w1v[c] = *reinterpret_cast<const float2*>(wb + pw * 2);
        w2v[c] = *reinterpret_cast<const float2*>(wb + pm * 2);
    }
    float whr[NCIN], whi[NCIN];
    #pragma unroll
    for (int c = 0; c < NCIN; c++) {
        whr[c] = 0.5f * (w1v[c].x + w2v[c].x);
        whi[c] = 0.5f * (w1v[c].y - w2v[c].y);
    }
    #pragma unroll
    for (int b = 0; b < NB; b++) {
        float gr = 0.f, gi = 0.f;
        #pragma unroll
        for (int c = 0; c < NCIN; c++) {
            const float2 f = g_F[(size_t)(b*NCIN + c)*HALFP + p];
            gr += f.x * whr[c] - f.y * whi[c];
            gi += f.x * whi[c] + f.y * whr[c];
        }
        g_G[(size_t)(b*NCOUT + o)*HALFP + p] = make_float2(gr, gi);
    }
}

// ---- stage 5: out[z] = Re(E5 @ T2[z]) + bias; 2 output cols per packed acc ----
// acc{c(n),c(n+1)} += {er,er}*{br(n),br(n+1)} + {-ei,-ei}*{bi(n),bi(n+1)}
__global__ void __launch_bounds__(128, 4) k_stage5(const float* __restrict__ bias,
                                                   float* __restrict__ out) {
    const int z = blockIdx.z;                   // b*NCOUT + o
    const float2* __restrict__ Bg = g_T2 + (size_t)z * SQ;
    float* __restrict__ O = out + (size_t)z * SQ;

    __shared__ u64 Ap[16][66], Aq[16][66];      // {er,er}, {-ei,-ei}
    __shared__ u64 Brp[16][34], Bip[16][34];    // {br,br'}, {bi,bi'} col pairs
    const int tid = threadIdx.x;
    const int tx = tid & 15, ty = tid >> 4;
    const int m0 = blockIdx.y * 64, n0 = blockIdx.x * 64;
    const int rw = tid >> 1, k8 = (tid & 1) * 8;
    const int kb0 = (tid >> 4) * 2, nb = (tid & 15) * 4;

    const float4* pA = reinterpret_cast<const float4*>(g_E5 + (size_t)(m0 + rw)*HH + k8);

    u64 acc[8][2] = {};

    for (int k0 = 0; k0 < HH; k0 += 16) {
        float4 a0 = pA[0], a1 = pA[1], a2 = pA[2], a3 = pA[3];  pA += 8;  // 16 complex
        Ap[k8+0][rw] = pk2(a0.x, a0.x);  Aq[k8+0][rw] = pk2(-a0.y, -a0.y);
        Ap[k8+1][rw] = pk2(a0.z, a0.z);  Aq[k8+1][rw] = pk2(-a0.w, -a0.w);
        Ap[k8+2][rw] = pk2(a1.x, a1.x);  Aq[k8+2][rw] = pk2(-a1.y, -a1.y);
        Ap[k8+3][rw] = pk2(a1.z, a1.z);  Aq[k8+3][rw] = pk2(-a1.w, -a1.w);
        Ap[k8+4][rw] = pk2(a2.x, a2.x);  Aq[k8+4][rw] = pk2(-a2.y, -a2.y);
        Ap[k8+5][rw] = pk2(a2.z, a2.z);  Aq[k8+5][rw] = pk2(-a2.w, -a2.w);
        Ap[k8+6][rw] = pk2(a3.x, a3.x);  Aq[k8+6][rw] = pk2(-a3.y, -a3.y);
        Ap[k8+7][rw] = pk2(a3.z, a3.z);  Aq[k8+7][rw] = pk2(-a3.w, -a3.w);
        // B: de-interleave T2 rows into col-pair packs
        float4 b00 = *reinterpret_cast<const float4*>(Bg + (size_t)(k0 + kb0)*HH + n0 + nb);
        float4 b01 = *reinterpret_cast<const float4*>(Bg + (size_t)(k0 + kb0)*HH + n0 + nb + 2);
        float4 b10 = *reinterpret_cast<const float4*>(Bg + (size_t)(k0 + kb0 + 1)*HH + n0 + nb);
        float4 b11 = *reinterpret_cast<const float4*>(Bg + (size_t)(k0 + kb0 + 1)*HH + n0 + nb + 2);
        Brp[kb0][(nb>>1)+0] = pk2(b00.x, b00.z);  Bip[kb0][(nb>>1)+0] = pk2(b00.y, b00.w);
        Brp[kb0][(nb>>1)+1] = pk2(b01.x, b01.z);  Bip[kb0][(nb>>1)+1] = pk2(b01.y, b01.w);
        Brp[kb0+1][(nb>>1)+0] = pk2(b10.x, b10.z);  Bip[kb0+1][(nb>>1)+0] = pk2(b10.y, b10.w);
        Brp[kb0+1][(nb>>1)+1] = pk2(b11.x, b11.z);  Bip[kb0+1][(nb>>1)+1] = pk2(b11.y, b11.w);
        __syncthreads();

        #pragma unroll 4
        for (int k = 0; k < 16; k++) {
            const u64* pap = &Ap[k][ty*8];
            const u64* paq = &Aq[k][ty*8];
            u64 er[8], en[8];
            #pragma unroll
            for (int i = 0; i < 8; i++) { er[i] = pap[i]; en[i] = paq[i]; }
            const float4* pbr = reinterpret_cast<const float4*>(&Brp[k][tx*2]);
            const float4* pbi = reinterpret_cast<const float4*>(&Bip[k][tx*2]);
            float4 r = pbr[0], s = pbi[0];
            u64 br[2] = { pk2(r.x, r.y), pk2(r.z, r.w) };
            u64 bi[2] = { pk2(s.x, s.y), pk2(s.z, s.w) };
            #pragma unroll
            for (int i = 0; i < 8; i++)
                #pragma unroll
                for (int j = 0; j < 2; j++) {
                    fma2(acc[i][j], er[i], br[j]);
                    fma2(acc[i][j], en[i], bi[j]);
                }
        }
        __syncthreads();
    }
    const float bv = bias[z & 7];
    #pragma unroll
    for (int i = 0; i < 8; i++) {
        const int gm = m0 + ty*8 + i;
        float2 c0 = upk(acc[i][0]), c1 = upk(acc[i][1]);
        *reinterpret_cast<float4*>(&O[(size_t)gm*HH + n0 + tx*4]) =
            make_float4(c0.x + bv, c0.y + bv, c1.x + bv, c1.y + bv);
    }
}

extern "C" void kernel_launch(void* const* d_in, const int* in_sizes, int n_in,
                              void* d_out, int out_size) {
    (void)in_sizes; (void)n_in; (void)out_size;
    const float* im   = (const float*)d_in[0];  // [4,4,256,256]
    const float* w    = (const float*)d_in[1];  // [8,4,511,511,2]
    const float* bias = (const float*)d_in[2];  // [8,1,1]
    float* out = (float*)d_out;                 // [4,8,256,256]

    k_twiddle<<<512, 256>>>();
    k_stage1 <<<dim3(4, 4, BC), 128>>>(im);                 // 256x256, K=256
    k_stage2 <<<dim3(8, 4, BC), 128>>>();                   // 256x512, K=256
    k_pointwise<<<dim3(HALFP / 256, NCOUT), 256>>>(w);      // padded half-plane
    k_stage4 <<<dim3(4, 4, BO), 128>>>();                   // 256x256, K=512
    k_stage5 <<<dim3(4, 4, BO), 128>>>(bias, out);          // 256x256, K=256
}

// round 8
// speedup vs baseline: 1.5779x; 1.5779x over previous
#include <cuda_runtime.h>

// FourierConv2D via DFT-as-GEMM (plain fp32 FFMA) with three symmetry folds:
//  1) real input  => only ky=0..255 of the 511-row spectrum (Hermitian rows)
//  2) forward col-DFT: F(511-kx) = sum T1*conj(A(kx)) => U/V/X/Y shared-product
//     accumulation yields F(kx) and F(511-kx) together at half the FMAs
//  3) inverse col-DFT: E(x,511-kx)=conj(E(x,kx)) => S=G+G', D=G-G' combine in
//     pointwise, K halves to 256: T2r=Sr Er - Di Ei, T2i=Si Er + Dr Ei
// Total ~9.6 GFLOP fp32. All arrays 256x256; no padding, no bounds checks.
// R8 fix: stage2 A-tile smem row stride 66 -> 68 floats (272B = 17*16) so
// float4 LDS stays 16B-aligned for odd k rows.

namespace {
constexpr int N5    = 511;
constexpr int HH    = 256;
constexpr int NB    = 4;
constexpr int NCIN  = 4;
constexpr int NCOUT = 8;
constexpr int PLANE = N5 * N5;
constexpr int SQ    = HH * HH;       // 65536
constexpr int BC    = NB * NCIN;     // 16
constexpr int BO    = NB * NCOUT;    // 32
}

// ---- scratch (device globals) ----
__device__ float  g_Ar[SQ],  g_Ai[SQ];   // A[kx][n] = exp(-2pi i kx n/511), kx,n 0..255
__device__ float2 g_E[SQ];               // {Er,Ei}[x][kx] = exp(+2pi i kx (x+127)/511)/511
__device__ float  g_E5r[SQ], g_E5i[SQ];  // E5[y][ky] = w(ky) exp(+2pi i ky (y+127)/511)
__device__ float  g_T1r[BC*SQ], g_T1i[BC*SQ];
__device__ float2 g_P[BC*SQ], g_Q[BC*SQ];   // F(kx), F(511-kx), kx=0..255
__device__ float4 g_SD[BO*SQ];              // {Sr,Si,Dr,Di}[ky][kx]
__device__ float  g_T2r[BO*SQ], g_T2i[BO*SQ];

// ---- twiddle init ----
__global__ void k_twiddle() {
    const int idx = blockIdx.x * blockDim.x + threadIdx.x;   // 0..65535
    const float TWO_PI = 6.283185307179586f;
    const int r = idx >> 8, c = idx & 255;
    {   // A[kx=r][n=c]
        int m = (r * c) % N5;
        float s, co; sincosf(TWO_PI * (float)m / (float)N5, &s, &co);
        g_Ar[idx] = co;  g_Ai[idx] = -s;
    }
    {   // E[x=r][kx=c]
        int m = (c * (r + 127)) % N5;
        float s, co; sincosf(TWO_PI * (float)m / (float)N5, &s, &co);
        const float inv = 1.0f / (float)N5;
        g_E[idx] = make_float2(co * inv, s * inv);
    }
    {   // E5[y=r][ky=c]
        int m = (c * (r + 127)) % N5;
        float s, co; sincosf(TWO_PI * (float)m / (float)N5, &s, &co);
        const float w = (c == 0) ? (1.0f / (float)N5) : (2.0f / (float)N5);
        g_E5r[idx] = co * w;  g_E5i[idx] = s * w;
    }
}

// ---- stage 1: T1[z] (256x256 cplx) = A[0:256] (cplx) @ X[z] (256x256 real) ----
__global__ void k_stage1(const float* __restrict__ im) {
    const int z = blockIdx.z;
    const float* __restrict__ X = im + (size_t)z * SQ;
    float* __restrict__ Cr = g_T1r + (size_t)z * SQ;
    float* __restrict__ Ci = g_T1i + (size_t)z * SQ;

    __shared__ float Asr[16][68], Asi[16][68], Bs[16][68];
    const int tx = threadIdx.x, ty = threadIdx.y;
    const int tid = ty * 16 + tx;
    const int m0 = blockIdx.y * 64, n0 = blockIdx.x * 64;
    const int ra = tid >> 2, ka = (tid & 3) * 4;
    const int kb = tid >> 4, nb = (tid & 15) * 4;

    float cr[4][4] = {}, ci[4][4] = {};

    for (int k0 = 0; k0 < HH; k0 += 16) {
        const int gm = m0 + ra;
        #pragma unroll
        for (int j = 0; j < 4; j++) {
            const int gk = k0 + ka + j;
            Asr[ka + j][ra] = g_Ar[gm*HH + gk];
            Asi[ka + j][ra] = g_Ai[gm*HH + gk];
        }
        #pragma unroll
        for (int j = 0; j < 4; j++)
            Bs[kb][nb + j] = X[(k0 + kb)*HH + n0 + nb + j];
        __syncthreads();

        #pragma unroll
        for (int k = 0; k < 16; k++) {
            float4 arv = *reinterpret_cast<const float4*>(&Asr[k][ty*4]);
            float4 aiv = *reinterpret_cast<const float4*>(&Asi[k][ty*4]);
            float4 bv  = *reinterpret_cast<const float4*>(&Bs[k][tx*4]);
            const float ar[4] = {arv.x, arv.y, arv.z, arv.w};
            const float ai[4] = {aiv.x, aiv.y, aiv.z, aiv.w};
            const float b [4] = {bv.x,  bv.y,  bv.z,  bv.w};
            #pragma unroll
            for (int i = 0; i < 4; i++)
                #pragma unroll
                for (int j = 0; j < 4; j++) {
                    cr[i][j] += ar[i] * b[j];
                    ci[i][j] += ai[i] * b[j];
                }
        }
        __syncthreads();
    }
    #pragma unroll
    for (int i = 0; i < 4; i++) {
        const int gm = m0 + ty*4 + i;
        #pragma unroll
        for (int j = 0; j < 4; j++) {
            const int gn = n0 + tx*4 + j;
            Cr[gm*HH + gn] = cr[i][j];
            Ci[gm*HH + gn] = ci[i][j];
        }
    }
}

// ---- stage 2: P,Q[z][ky][kx] for kx=0..255 via shared products ----
// U=sum T1r*Ar, V=sum T1i*Ai, X=sum T1r*Ai, Y=sum T1i*Ar  (over n)
// P = (U-V, X+Y) = F(kx);  Q = (U+V, Y-X) = F(511-kx)
// Block: 64(ky) x 32(kx), 128 threads, 8x2 outputs/thread.
__global__ void __launch_bounds__(128) k_stage2() {
    const int z = blockIdx.z;
    const float* __restrict__ T1r = g_T1r + (size_t)z * SQ;
    const float* __restrict__ T1i = g_T1i + (size_t)z * SQ;
    float2* __restrict__ P = g_P + (size_t)z * SQ;
    float2* __restrict__ Q = g_Q + (size_t)z * SQ;

    __shared__ float Asr[16][68], Asi[16][68];   // T1 tile: k(n) x 64 ky-rows (68: keep 16B align)
    __shared__ float Bsr[16][34], Bsi[16][34];   // A tile:  k(n) x 32 kx-rows (float2 reads only)
    const int tid = threadIdx.x;
    const int tx = tid & 15, ty = tid >> 4;      // cols tx*2, rows ty*8
    const int m0 = blockIdx.y * 64, n0 = blockIdx.x * 32;
    const int rw = tid >> 1, k8 = (tid & 1) * 8;   // A loader
    const int rb = tid >> 2, kq = (tid & 3) * 4;   // B loader

    float U[8][2] = {}, V[8][2] = {}, Xc[8][2] = {}, Yc[8][2] = {};

    for (int k0 = 0; k0 < HH; k0 += 16) {
        {   float4 r0 = *reinterpret_cast<const float4*>(T1r + (size_t)(m0 + rw)*HH + k0 + k8);
            float4 r1 = *reinterpret_cast<const float4*>(T1r + (size_t)(m0 + rw)*HH + k0 + k8 + 4);
            float4 i0 = *reinterpret_cast<const float4*>(T1i + (size_t)(m0 + rw)*HH + k0 + k8);
            float4 i1 = *reinterpret_cast<const float4*>(T1i + (size_t)(m0 + rw)*HH + k0 + k8 + 4);
            Asr[k8+0][rw]=r0.x; Asr[k8+1][rw]=r0.y; Asr[k8+2][rw]=r0.z; Asr[k8+3][rw]=r0.w;
            Asr[k8+4][rw]=r1.x; Asr[k8+5][rw]=r1.y; Asr[k8+6][rw]=r1.z; Asr[k8+7][rw]=r1.w;
            Asi[k8+0][rw]=i0.x; Asi[k8+1][rw]=i0.y; Asi[k8+2][rw]=i0.z; Asi[k8+3][rw]=i0.w;
            Asi[k8+4][rw]=i1.x; Asi[k8+5][rw]=i1.y; Asi[k8+6][rw]=i1.z; Asi[k8+7][rw]=i1.w;
        }
        {   float4 r0 = *reinterpret_cast<const float4*>(g_Ar + (size_t)(n0 + rb)*HH + k0 + kq);
            float4 i0 = *reinterpret_cast<const float4*>(g_Ai + (size_t)(n0 + rb)*HH + k0 + kq);
            Bsr[kq+0][rb]=r0.x; Bsr[kq+1][rb]=r0.y; Bsr[kq+2][rb]=r0.z; Bsr[kq+3][rb]=r0.w;
            Bsi[kq+0][rb]=i0.x; Bsi[kq+1][rb]=i0.y; Bsi[kq+2][rb]=i0.z; Bsi[kq+3][rb]=i0.w;
        }
        __syncthreads();

        #pragma unroll 4
        for (int k = 0; k < 16; k++) {
            float4 tr0 = *reinterpret_cast<const float4*>(&Asr[k][ty*8]);
            float4 tr1 = *reinterpret_cast<const float4*>(&Asr[k][ty*8+4]);
            float4 ti0 = *reinterpret_cast<const float4*>(&Asi[k][ty*8]);
            float4 ti1 = *reinterpret_cast<const float4*>(&Asi[k][ty*8+4]);
            float2 br  = *reinterpret_cast<const float2*>(&Bsr[k][tx*2]);
            float2 bi  = *reinterpret_cast<const float2*>(&Bsi[k][tx*2]);
            const float ar[8] = {tr0.x,tr0.y,tr0.z,tr0.w,tr1.x,tr1.y,tr1.z,tr1.w};
            const float ai[8] = {ti0.x,ti0.y,ti0.z,ti0.w,ti1.x,ti1.y,ti1.z,ti1.w};
            const float wr[2] = {br.x, br.y};
            const float wi[2] = {bi.x, bi.y};
            #pragma unroll
            for (int i = 0; i < 8; i++)
                #pragma unroll
                for (int j = 0; j < 2; j++) {
                    U [i][j] += ar[i] * wr[j];
                    V [i][j] += ai[i] * wi[j];
                    Xc[i][j] += ar[i] * wi[j];
                    Yc[i][j] += ai[i] * wr[j];
                }
        }
        __syncthreads();
    }
    #pragma unroll
    for (int i = 0; i < 8; i++) {
        const int gm = m0 + ty*8 + i;
        const int gn = n0 + tx*2;
        float4 pv = make_float4(U[i][0]-V[i][0], Xc[i][0]+Yc[i][0],
                                U[i][1]-V[i][1], Xc[i][1]+Yc[i][1]);
        float4 qv = make_float4(U[i][0]+V[i][0], Yc[i][0]-Xc[i][0],
                                U[i][1]+V[i][1], Yc[i][1]-Xc[i][1]);
        *reinterpret_cast<float4*>(P + (size_t)gm*HH + gn) = pv;
        *reinterpret_cast<float4*>(Q + (size_t)gm*HH + gn) = qv;
    }
}

// ---- stage 3: pointwise Hermitian-W multiply + cin sum + S/D combine ----
__global__ void k_pointwise(const float* __restrict__ w) {
    const int p = blockIdx.x * blockDim.x + threadIdx.x;  // ky*256+kx
    const int o = blockIdx.y;
    const int ky = p >> 8, kx = p & 255;
    const int ky2 = (N5 - ky) % N5;
    const int kx2 = (N5 - kx) % N5;

    float2 wh1[NCIN], wh2[NCIN];
    #pragma unroll
    for (int c = 0; c < NCIN; c++) {
        const float* wb = w + (size_t)(o*NCIN + c) * PLANE * 2;
        const float2 a = *reinterpret_cast<const float2*>(wb + ((size_t)ky *N5 + kx )*2);
        const float2 bq= *reinterpret_cast<const float2*>(wb + ((size_t)ky2*N5 + kx2)*2);
        wh1[c] = make_float2(0.5f*(a.x + bq.x), 0.5f*(a.y - bq.y));
        if (kx != 0) {
            const float2 e = *reinterpret_cast<const float2*>(wb + ((size_t)ky *N5 + (N5-kx))*2);
            const float2 f = *reinterpret_cast<const float2*>(wb + ((size_t)ky2*N5 + kx     )*2);
            wh2[c] = make_float2(0.5f*(e.x + f.x), 0.5f*(e.y - f.y));
        } else {
            wh2[c] = make_float2(0.f, 0.f);
        }
    }
    #pragma unroll
    for (int b = 0; b < NB; b++) {
        float gr = 0.f, gi = 0.f, hr = 0.f, hi = 0.f;   // G, G'
        #pragma unroll
        for (int c = 0; c < NCIN; c++) {
            const float2 Pv = g_P[(size_t)(b*NCIN + c)*SQ + p];
            const float2 Qv = g_Q[(size_t)(b*NCIN + c)*SQ + p];
            gr += Pv.x * wh1[c].x - Pv.y * wh1[c].y;
            gi += Pv.x * wh1[c].y + Pv.y * wh1[c].x;
            hr += Qv.x * wh2[c].x - Qv.y * wh2[c].y;
            hi += Qv.x * wh2[c].y + Qv.y * wh2[c].x;
        }
        g_SD[(size_t)(b*NCOUT + o)*SQ + p] =
            make_float4(gr + hr, gi + hi, gr - hr, gi - hi);
    }
}

// ---- stage 4: T2[z] (256x256 cplx) from SD @ {Er,Ei}, K=256 ----
// T2r = Sr@Er^T - Di@Ei^T ;  T2i = Si@Er^T + Dr@Ei^T
__global__ void __launch_bounds__(128) k_stage4() {
    const int z = blockIdx.z;
    const float4* __restrict__ Ag = g_SD + (size_t)z * SQ;
    float* __restrict__ Cr = g_T2r + (size_t)z * SQ;
    float* __restrict__ Ci = g_T2i + (size_t)z * SQ;

    __shared__ float4 As[16][65];     // k(kx) x 64 ky-rows: {Sr,Si,Dr,Di}
    __shared__ float2 Bs[16][66];     // k(kx) x 64 x-rows:  {Er,Ei}
    const int tid = threadIdx.x;
    const int tx = tid & 15, ty = tid >> 4;
    const int m0 = blockIdx.y * 64, n0 = blockIdx.x * 64;
    const int rw = tid >> 1, k8 = (tid & 1) * 8;

    float t2r[8][4] = {}, t2i[8][4] = {};

    for (int k0 = 0; k0 < HH; k0 += 16) {
        #pragma unroll
        for (int j = 0; j < 8; j++)
            As[k8 + j][rw] = Ag[(size_t)(m0 + rw)*HH + k0 + k8 + j];
        #pragma unroll
        for (int j = 0; j < 8; j++)
            Bs[k8 + j][rw] = g_E[(size_t)(n0 + rw)*HH + k0 + k8 + j];
        __syncthreads();

        #pragma unroll 2
        for (int k = 0; k < 16; k++) {
            float4 a[8];
            #pragma unroll
            for (int i = 0; i < 8; i++) a[i] = As[k][ty*8 + i];
            float2 b[4];
            #pragma unroll
            for (int j = 0; j < 4; j++) b[j] = Bs[k][tx*4 + j];
            #pragma unroll
            for (int i = 0; i < 8; i++)
                #pragma unroll
                for (int j = 0; j < 4; j++) {
                    t2r[i][j] += a[i].x * b[j].x;
                    t2r[i][j] -= a[i].w * b[j].y;
                    t2i[i][j] += a[i].y * b[j].x;
                    t2i[i][j] += a[i].z * b[j].y;
                }
        }
        __syncthreads();
    }
    #pragma unroll
    for (int i = 0; i < 8; i++) {
        const int gm = m0 + ty*8 + i;
        *reinterpret_cast<float4*>(Cr + (size_t)gm*HH + n0 + tx*4) =
            make_float4(t2r[i][0], t2r[i][1], t2r[i][2], t2r[i][3]);
        *reinterpret_cast<float4*>(Ci + (size_t)gm*HH + n0 + tx*4) =
            make_float4(t2i[i][0], t2i[i][1], t2i[i][2], t2i[i][3]);
    }
}

// ---- stage 5: out[z] = E5r @ T2r - E5i @ T2i + bias ----
__global__ void __launch_bounds__(128) k_stage5(const float* __restrict__ bias,
                                                float* __restrict__ out) {
    const int z = blockIdx.z;                   // b*NCOUT + o
    const float* __restrict__ Br = g_T2r + (size_t)z * SQ;
    const float* __restrict__ Bi = g_T2i + (size_t)z * SQ;
    float* __restrict__ O = out + (size_t)z * SQ;

    __shared__ float Asr[16][68], Asi[16][68], Bsr[16][68], Bsi[16][68];
    const int tid = threadIdx.x;
    const int tx = tid & 15, ty = tid >> 4;
    const int m0 = blockIdx.y * 64, n0 = blockIdx.x * 64;
    const int rw = tid >> 1, k8 = (tid & 1) * 8;
    const int kb0 = (tid >> 4) * 2, nb0 = (tid & 15) * 4;

    const float* pAr = g_E5r + (size_t)(m0 + rw)*HH + k8;
    const float* pAi = g_E5i + (size_t)(m0 + rw)*HH + k8;

    float acc[8][4] = {};

    for (int k0 = 0; k0 < HH; k0 += 16) {
        float4 a0 = *reinterpret_cast<const float4*>(pAr);
        float4 a1 = *reinterpret_cast<const float4*>(pAr + 4);
        float4 a2 = *reinterpret_cast<const float4*>(pAi);
        float4 a3 = *reinterpret_cast<const float4*>(pAi + 4);
        pAr += 16; pAi += 16;
        float4 br0 = *reinterpret_cast<const float4*>(&Br[(size_t)(k0 + kb0)*HH + n0 + nb0]);
        float4 br1 = *reinterpret_cast<const float4*>(&Br[(size_t)(k0 + kb0 + 1)*HH + n0 + nb0]);
        float4 bi0 = *reinterpret_cast<const float4*>(&Bi[(size_t)(k0 + kb0)*HH + n0 + nb0]);
        float4 bi1 = *reinterpret_cast<const float4*>(&Bi[(size_t)(k0 + kb0 + 1)*HH + n0 + nb0]);

        const float ar8[8] = {a0.x,a0.y,a0.z,a0.w,a1.x,a1.y,a1.z,a1.w};
        const float ai8[8] = {a2.x,a2.y,a2.z,a2.w,a3.x,a3.y,a3.z,a3.w};
        #pragma unroll
        for (int j = 0; j < 8; j++) {
            Asr[k8 + j][rw] = ar8[j];
            Asi[k8 + j][rw] = ai8[j];
        }
        *reinterpret_cast<float4*>(&Bsr[kb0][nb0])     = br0;
        *reinterpret_cast<float4*>(&Bsr[kb0 + 1][nb0]) = br1;
        *reinterpret_cast<float4*>(&Bsi[kb0][nb0])     = bi0;
        *reinterpret_cast<float4*>(&Bsi[kb0 + 1][nb0]) = bi1;
        __syncthreads();

        #pragma unroll 4
        for (int k = 0; k < 16; k++) {
            float4 xr0 = *reinterpret_cast<const float4*>(&Asr[k][ty*8]);
            float4 xr1 = *reinterpret_cast<const float4*>(&Asr[k][ty*8+4]);
            float4 xi0 = *reinterpret_cast<const float4*>(&Asi[k][ty*8]);
            float4 xi1 = *reinterpret_cast<const float4*>(&Asi[k][ty*8+4]);
            float4 yr  = *reinterpret_cast<const float4*>(&Bsr[k][tx*4]);
            float4 yi  = *reinterpret_cast<const float4*>(&Bsi[k][tx*4]);
            const float er[8] = {xr0.x,xr0.y,xr0.z,xr0.w,xr1.x,xr1.y,xr1.z,xr1.w};
            const float ei[8] = {xi0.x,xi0.y,xi0.z,xi0.w,xi1.x,xi1.y,xi1.z,xi1.w};
            const float br[4] = {yr.x,yr.y,yr.z,yr.w};
            const float bi[4] = {yi.x,yi.y,yi.z,yi.w};
            #pragma unroll
            for (int i = 0; i < 8; i++)
                #pragma unroll
                for (int j = 0; j < 4; j++)
                    acc[i][j] += er[i] * br[j] - ei[i] * bi[j];
        }
        __syncthreads();
    }
    const float bv = bias[z & 7];
    #pragma unroll
    for (int i = 0; i < 8; i++) {
        const int gm = m0 + ty*8 + i;
        float4 v = {acc[i][0] + bv, acc[i][1] + bv, acc[i][2] + bv, acc[i][3] + bv};
        *reinterpret_cast<float4*>(&O[(size_t)gm*HH + n0 + tx*4]) = v;
    }
}

extern "C" void kernel_launch(void* const* d_in, const int* in_sizes, int n_in,
                              void* d_out, int out_size) {
    (void)in_sizes; (void)n_in; (void)out_size;
    const float* im   = (const float*)d_in[0];  // [4,4,256,256]
    const float* w    = (const float*)d_in[1];  // [8,4,511,511,2]
    const float* bias = (const float*)d_in[2];  // [8,1,1]
    float* out = (float*)d_out;                 // [4,8,256,256]

    k_twiddle<<<256, 256>>>();
    k_stage1 <<<dim3(4, 4, BC), dim3(16, 16)>>>(im);   // 256x256 c, K=256
    k_stage2 <<<dim3(8, 4, BC), 128>>>();              // P,Q 256x256, K=256
    k_pointwise<<<dim3(SQ / 256, NCOUT), 256>>>(w);    // 256x256 grid
    k_stage4 <<<dim3(4, 4, BO), 128>>>();              // 256x256 c, K=256
    k_stage5 <<<dim3(4, 4, BO), 128>>>(bias, out);     // 256x256 r, K=256
}

// round 9
// speedup vs baseline: 1.7686x; 1.1208x over previous
#include <cuda_runtime.h>

// FourierConv2D via DFT-as-GEMM (plain fp32 FFMA) with five symmetry folds:
//  1) real input => only ky=0..255 of the 511-row spectrum
//  2) forward col-DFT: P/Q shared-product pairs give F(kx), F(511-kx) together
//  3) inverse col-DFT K-fold: S=G+G', D=G-G' => K=256
//  4) inverse col-DFT x-fold: Ec[257-x]=conj(Ec[x]) => distinct x=0..127 (+tail 128/129)
//  5) row-inverse y-fold: E5[257-y]=conj(E5[y]) => distinct y=0..127 (+tail 128/129)
// Total ~6.4 GFLOP fp32.

namespace {
constexpr int N5    = 511;
constexpr int HH    = 256;
constexpr int NB    = 4;
constexpr int NCIN  = 4;
constexpr int NCOUT = 8;
constexpr int PLANE = N5 * N5;
constexpr int SQ    = HH * HH;       // 65536
constexpr int BC    = NB * NCIN;     // 16
constexpr int BO    = NB * NCOUT;    // 32
}

// ---- scratch (device globals) ----
__device__ float  g_Ar[SQ],  g_Ai[SQ];   // A[kx][n] = exp(-2pi i kx n/511)
__device__ float2 g_E[SQ];               // {Er,Ei}[x][kx] = exp(+2pi i kx (x+127)/511)/511
__device__ float  g_E5r[SQ], g_E5i[SQ];  // E5[y][ky] = w(ky) exp(+2pi i ky (y+127)/511)
__device__ float  g_T1r[BC*SQ], g_T1i[BC*SQ];
__device__ float2 g_P[BC*SQ], g_Q[BC*SQ];   // F(kx), F(511-kx), kx=0..255
__device__ float4 g_SD[BO*SQ];              // {Sr,Si,Dr,Di}[ky][kx]
__device__ float  g_T2r[BO*SQ], g_T2i[BO*SQ];

// ---- twiddle init ----
__global__ void k_twiddle() {
    const int idx = blockIdx.x * blockDim.x + threadIdx.x;   // 0..65535
    const float TWO_PI = 6.283185307179586f;
    const int r = idx >> 8, c = idx & 255;
    {   // A[kx=r][n=c]
        int m = (r * c) % N5;
        float s, co; sincosf(TWO_PI * (float)m / (float)N5, &s, &co);
        g_Ar[idx] = co;  g_Ai[idx] = -s;
    }
    {   // E[x=r][kx=c]
        int m = (c * (r + 127)) % N5;
        float s, co; sincosf(TWO_PI * (float)m / (float)N5, &s, &co);
        const float inv = 1.0f / (float)N5;
        g_E[idx] = make_float2(co * inv, s * inv);
    }
    {   // E5[y=r][ky=c]
        int m = (c * (r + 127)) % N5;
        float s, co; sincosf(TWO_PI * (float)m / (float)N5, &s, &co);
        const float w = (c == 0) ? (1.0f / (float)N5) : (2.0f / (float)N5);
        g_E5r[idx] = co * w;  g_E5i[idx] = s * w;
    }
}

// ---- stage 1: T1[z] (256x256 cplx) = A[0:256] (cplx) @ X[z] (256x256 real) ----
__global__ void k_stage1(const float* __restrict__ im) {
    const int z = blockIdx.z;
    const float* __restrict__ X = im + (size_t)z * SQ;
    float* __restrict__ Cr = g_T1r + (size_t)z * SQ;
    float* __restrict__ Ci = g_T1i + (size_t)z * SQ;

    __shared__ float Asr[16][68], Asi[16][68], Bs[16][68];
    const int tx = threadIdx.x, ty = threadIdx.y;
    const int tid = ty * 16 + tx;
    const int m0 = blockIdx.y * 64, n0 = blockIdx.x * 64;
    const int ra = tid >> 2, ka = (tid & 3) * 4;
    const int kb = tid >> 4, nb = (tid & 15) * 4;

    float cr[4][4] = {}, ci[4][4] = {};

    for (int k0 = 0; k0 < HH; k0 += 16) {
        const int gm = m0 + ra;
        #pragma unroll
        for (int j = 0; j < 4; j++) {
            const int gk = k0 + ka + j;
            Asr[ka + j][ra] = g_Ar[gm*HH + gk];
            Asi[ka + j][ra] = g_Ai[gm*HH + gk];
        }
        #pragma unroll
        for (int j = 0; j < 4; j++)
            Bs[kb][nb + j] = X[(k0 + kb)*HH + n0 + nb + j];
        __syncthreads();

        #pragma unroll
        for (int k = 0; k < 16; k++) {
            float4 arv = *reinterpret_cast<const float4*>(&Asr[k][ty*4]);
            float4 aiv = *reinterpret_cast<const float4*>(&Asi[k][ty*4]);
            float4 bv  = *reinterpret_cast<const float4*>(&Bs[k][tx*4]);
            const float ar[4] = {arv.x, arv.y, arv.z, arv.w};
            const float ai[4] = {aiv.x, aiv.y, aiv.z, aiv.w};
            const float b [4] = {bv.x,  bv.y,  bv.z,  bv.w};
            #pragma unroll
            for (int i = 0; i < 4; i++)
                #pragma unroll
                for (int j = 0; j < 4; j++) {
                    cr[i][j] += ar[i] * b[j];
                    ci[i][j] += ai[i] * b[j];
                }
        }
        __syncthreads();
    }
    #pragma unroll
    for (int i = 0; i < 4; i++) {
        const int gm = m0 + ty*4 + i;
        #pragma unroll
        for (int j = 0; j < 4; j++) {
            const int gn = n0 + tx*4 + j;
            Cr[gm*HH + gn] = cr[i][j];
            Ci[gm*HH + gn] = ci[i][j];
        }
    }
}

// ---- stage 2: P,Q[z][ky][kx] for kx=0..255 via shared products ----
__global__ void __launch_bounds__(128) k_stage2() {
    const int z = blockIdx.z;
    const float* __restrict__ T1r = g_T1r + (size_t)z * SQ;
    const float* __restrict__ T1i = g_T1i + (size_t)z * SQ;
    float2* __restrict__ P = g_P + (size_t)z * SQ;
    float2* __restrict__ Q = g_Q + (size_t)z * SQ;

    __shared__ float Asr[16][68], Asi[16][68];
    __shared__ float Bsr[16][34], Bsi[16][34];
    const int tid = threadIdx.x;
    const int tx = tid & 15, ty = tid >> 4;
    const int m0 = blockIdx.y * 64, n0 = blockIdx.x * 32;
    const int rw = tid >> 1, k8 = (tid & 1) * 8;
    const int rb = tid >> 2, kq = (tid & 3) * 4;

    float U[8][2] = {}, V[8][2] = {}, Xc[8][2] = {}, Yc[8][2] = {};

    for (int k0 = 0; k0 < HH; k0 += 16) {
        {   float4 r0 = *reinterpret_cast<const float4*>(T1r + (size_t)(m0 + rw)*HH + k0 + k8);
            float4 r1 = *reinterpret_cast<const float4*>(T1r + (size_t)(m0 + rw)*HH + k0 + k8 + 4);
            float4 i0 = *reinterpret_cast<const float4*>(T1i + (size_t)(m0 + rw)*HH + k0 + k8);
            float4 i1 = *reinterpret_cast<const float4*>(T1i + (size_t)(m0 + rw)*HH + k0 + k8 + 4);
            Asr[k8+0][rw]=r0.x; Asr[k8+1][rw]=r0.y; Asr[k8+2][rw]=r0.z; Asr[k8+3][rw]=r0.w;
            Asr[k8+4][rw]=r1.x; Asr[k8+5][rw]=r1.y; Asr[k8+6][rw]=r1.z; Asr[k8+7][rw]=r1.w;
            Asi[k8+0][rw]=i0.x; Asi[k8+1][rw]=i0.y; Asi[k8+2][rw]=i0.z; Asi[k8+3][rw]=i0.w;
            Asi[k8+4][rw]=i1.x; Asi[k8+5][rw]=i1.y; Asi[k8+6][rw]=i1.z; Asi[k8+7][rw]=i1.w;
        }
        {   float4 r0 = *reinterpret_cast<const float4*>(g_Ar + (size_t)(n0 + rb)*HH + k0 + kq);
            float4 i0 = *reinterpret_cast<const float4*>(g_Ai + (size_t)(n0 + rb)*HH + k0 + kq);
            Bsr[kq+0][rb]=r0.x; Bsr[kq+1][rb]=r0.y; Bsr[kq+2][rb]=r0.z; Bsr[kq+3][rb]=r0.w;
            Bsi[kq+0][rb]=i0.x; Bsi[kq+1][rb]=i0.y; Bsi[kq+2][rb]=i0.z; Bsi[kq+3][rb]=i0.w;
        }
        __syncthreads();

        #pragma unroll 4
        for (int k = 0; k < 16; k++) {
            float4 tr0 = *reinterpret_cast<const float4*>(&Asr[k][ty*8]);
            float4 tr1 = *reinterpret_cast<const float4*>(&Asr[k][ty*8+4]);
            float4 ti0 = *reinterpret_cast<const float4*>(&Asi[k][ty*8]);
            float4 ti1 = *reinterpret_cast<const float4*>(&Asi[k][ty*8+4]);
            float2 br  = *reinterpret_cast<const float2*>(&Bsr[k][tx*2]);
            float2 bi  = *reinterpret_cast<const float2*>(&Bsi[k][tx*2]);
            const float ar[8] = {tr0.x,tr0.y,tr0.z,tr0.w,tr1.x,tr1.y,tr1.z,tr1.w};
            const float ai[8] = {ti0.x,ti0.y,ti0.z,ti0.w,ti1.x,ti1.y,ti1.z,ti1.w};
            const float wr[2] = {br.x, br.y};
            const float wi[2] = {bi.x, bi.y};
            #pragma unroll
            for (int i = 0; i < 8; i++)
                #pragma unroll
                for (int j = 0; j < 2; j++) {
                    U [i][j] += ar[i] * wr[j];
                    V [i][j] += ai[i] * wi[j];
                    Xc[i][j] += ar[i] * wi[j];
                    Yc[i][j] += ai[i] * wr[j];
                }
        }
        __syncthreads();
    }
    #pragma unroll
    for (int i = 0; i < 8; i++) {
        const int gm = m0 + ty*8 + i;
        const int gn = n0 + tx*2;
        float4 pv = make_float4(U[i][0]-V[i][0], Xc[i][0]+Yc[i][0],
                                U[i][1]-V[i][1], Xc[i][1]+Yc[i][1]);
        float4 qv = make_float4(U[i][0]+V[i][0], Yc[i][0]-Xc[i][0],
                                U[i][1]+V[i][1], Yc[i][1]-Xc[i][1]);
        *reinterpret_cast<float4*>(P + (size_t)gm*HH + gn) = pv;
        *reinterpret_cast<float4*>(Q + (size_t)gm*HH + gn) = qv;
    }
}

// ---- stage 3: pointwise Hermitian-W multiply + cin sum + S/D combine ----
__global__ void k_pointwise(const float* __restrict__ w) {
    const int p = blockIdx.x * blockDim.x + threadIdx.x;  // ky*256+kx
    const int o = blockIdx.y;
    const int ky = p >> 8, kx = p & 255;
    const int ky2 = (N5 - ky) % N5;
    const int kx2 = (N5 - kx) % N5;

    float2 wh1[NCIN], wh2[NCIN];
    #pragma unroll
    for (int c = 0; c < NCIN; c++) {
        const float* wb = w + (size_t)(o*NCIN + c) * PLANE * 2;
        const float2 a = *reinterpret_cast<const float2*>(wb + ((size_t)ky *N5 + kx )*2);
        const float2 bq= *reinterpret_cast<const float2*>(wb + ((size_t)ky2*N5 + kx2)*2);
        wh1[c] = make_float2(0.5f*(a.x + bq.x), 0.5f*(a.y - bq.y));
        if (kx != 0) {
            const float2 e = *reinterpret_cast<const float2*>(wb + ((size_t)ky *N5 + (N5-kx))*2);
            const float2 f = *reinterpret_cast<const float2*>(wb + ((size_t)ky2*N5 + kx     )*2);
            wh2[c] = make_float2(0.5f*(e.x + f.x), 0.5f*(e.y - f.y));
        } else {
            wh2[c] = make_float2(0.f, 0.f);
        }
    }
    #pragma unroll
    for (int b = 0; b < NB; b++) {
        float gr = 0.f, gi = 0.f, hr = 0.f, hi = 0.f;   // G, G'
        #pragma unroll
        for (int c = 0; c < NCIN; c++) {
            const float2 Pv = g_P[(size_t)(b*NCIN + c)*SQ + p];
            const float2 Qv = g_Q[(size_t)(b*NCIN + c)*SQ + p];
            gr += Pv.x * wh1[c].x - Pv.y * wh1[c].y;
            gi += Pv.x * wh1[c].y + Pv.y * wh1[c].x;
            hr += Qv.x * wh2[c].x - Qv.y * wh2[c].y;
            hi += Qv.x * wh2[c].y + Qv.y * wh2[c].x;
        }
        g_SD[(size_t)(b*NCOUT + o)*SQ + p] =
            make_float4(gr + hr, gi + hi, gr - hr, gi - hi);
    }
}

// ---- stage 4 (x-folded): distinct cols t=0..127 (x=t), partners x=257-t (t>=2) ----
// P=Sum Sr*Er, Q=Sum Di*Ei, R=Sum Si*Er, T=Sum Dr*Ei  over kx
// T2[ky][t] = (P-Q, R+T);  T2[ky][257-t] = (P+Q, R-T)
__global__ void __launch_bounds__(128) k_stage4() {
    const int z = blockIdx.z;
    const float4* __restrict__ Ag = g_SD + (size_t)z * SQ;
    float* __restrict__ Cr = g_T2r + (size_t)z * SQ;
    float* __restrict__ Ci = g_T2i + (size_t)z * SQ;

    __shared__ float4 As[16][65];     // [k][ky-row]: {Sr,Si,Dr,Di}
    __shared__ float2 Bs[16][34];     // [k][col t]: {Er,Ei}; 34*8=272B row = 17*16 (float4-safe)
    const int tid = threadIdx.x;
    const int tx = tid & 15, ty = tid >> 4;       // 16 col-groups x 2, 8 row-groups x 8
    const int m0 = blockIdx.y * 64, n0 = blockIdx.x * 32;
    const int rw = tid >> 1, k8 = (tid & 1) * 8;  // A loader: 64 rows x 2 k-halves
    const int rb = tid & 31, kb = (tid >> 2) & ~3;// B loader: 32 cols x 4 k-quads
    const int kb4 = (tid >> 5) * 4;               // k offsets {0,4,8,12}

    float P[8][2] = {}, Q[8][2] = {}, R[8][2] = {}, T[8][2] = {};
    (void)kb;

    for (int k0 = 0; k0 < HH; k0 += 16) {
        #pragma unroll
        for (int j = 0; j < 8; j++)
            As[k8 + j][rw] = Ag[(size_t)(m0 + rw)*HH + k0 + k8 + j];
        #pragma unroll
        for (int j = 0; j < 4; j++)
            Bs[kb4 + j][rb] = g_E[(size_t)(n0 + rb)*HH + k0 + kb4 + j];
        __syncthreads();

        #pragma unroll 2
        for (int k = 0; k < 16; k++) {
            float4 a[8];
            #pragma unroll
            for (int i = 0; i < 8; i++) a[i] = As[k][ty*8 + i];
            float4 bvec = *reinterpret_cast<const float4*>(&Bs[k][tx*2]); // {Er0,Ei0,Er1,Ei1}
            const float er[2] = {bvec.x, bvec.z};
            const float ei[2] = {bvec.y, bvec.w};
            #pragma unroll
            for (int i = 0; i < 8; i++)
                #pragma unroll
                for (int j = 0; j < 2; j++) {
                    P[i][j] += a[i].x * er[j];   // Sr*Er
                    Q[i][j] += a[i].w * ei[j];   // Di*Ei
                    R[i][j] += a[i].y * er[j];   // Si*Er
                    T[i][j] += a[i].z * ei[j];   // Dr*Ei
                }
        }
        __syncthreads();
    }
    const int t0 = n0 + tx*2;
    #pragma unroll
    for (int i = 0; i < 8; i++) {
        const int gm = m0 + ty*8 + i;
        *reinterpret_cast<float2*>(Cr + (size_t)gm*HH + t0) =
            make_float2(P[i][0]-Q[i][0], P[i][1]-Q[i][1]);
        *reinterpret_cast<float2*>(Ci + (size_t)gm*HH + t0) =
            make_float2(R[i][0]+T[i][0], R[i][1]+T[i][1]);
        if (t0 >= 2) {   // partner cols (256-t0, 257-t0) = (t0+1, t0) reversed
            *reinterpret_cast<float2*>(Cr + (size_t)gm*HH + 256 - t0) =
                make_float2(P[i][1]+Q[i][1], P[i][0]+Q[i][0]);
            *reinterpret_cast<float2*>(Ci + (size_t)gm*HH + 256 - t0) =
                make_float2(R[i][1]-T[i][1], R[i][0]-T[i][0]);
        }
    }
}

// ---- stage 4 tail: T2 cols 128,129 from E row 128 (129 = conj partner) ----
__global__ void k_tail4() {
    const int z = blockIdx.y;
    const int warp = threadIdx.x >> 5, lane = threadIdx.x & 31;
    const int ky = blockIdx.x * 8 + warp;
    const float4* __restrict__ Arow = g_SD + (size_t)z * SQ + (size_t)ky * HH;
    float P = 0.f, Q = 0.f, R = 0.f, T = 0.f;
    for (int kx = lane; kx < HH; kx += 32) {
        const float4 a = Arow[kx];
        const float2 e = g_E[128*HH + kx];
        P += a.x * e.x;  Q += a.w * e.y;
        R += a.y * e.x;  T += a.z * e.y;
    }
    #pragma unroll
    for (int off = 16; off; off >>= 1) {
        P += __shfl_down_sync(0xffffffffu, P, off);
        Q += __shfl_down_sync(0xffffffffu, Q, off);
        R += __shfl_down_sync(0xffffffffu, R, off);
        T += __shfl_down_sync(0xffffffffu, T, off);
    }
    if (lane == 0) {
        float* Cr = g_T2r + (size_t)z * SQ + (size_t)ky * HH;
        float* Ci = g_T2i + (size_t)z * SQ + (size_t)ky * HH;
        Cr[128] = P - Q;  Ci[128] = R + T;
        Cr[129] = P + Q;  Ci[129] = R - T;
    }
}

// ---- stage 5 (y-folded): distinct rows y=0..127, partner rows 257-y (y>=2) ----
// P=Sum E5r*T2r, Q=Sum E5i*T2i;  out[y]=P-Q+b;  out[257-y]=P+Q+b
__global__ void __launch_bounds__(128) k_stage5(const float* __restrict__ bias,
                                                float* __restrict__ out) {
    const int z = blockIdx.z;
    const float* __restrict__ Br = g_T2r + (size_t)z * SQ;
    const float* __restrict__ Bi = g_T2i + (size_t)z * SQ;
    float* __restrict__ O = out + (size_t)z * SQ;

    __shared__ float Asr[16][68], Asi[16][68], Bsr[16][68], Bsi[16][68];
    const int tid = threadIdx.x;
    const int tx = tid & 15, ty = tid >> 4;
    const int m0 = blockIdx.y * 64, n0 = blockIdx.x * 64;   // m0 in {0,64}
    const int rw = tid >> 1, k8 = (tid & 1) * 8;
    const int kb0 = (tid >> 4) * 2, nb0 = (tid & 15) * 4;

    const float* pAr = g_E5r + (size_t)(m0 + rw)*HH + k8;
    const float* pAi = g_E5i + (size_t)(m0 + rw)*HH + k8;

    float P[8][4] = {}, Q[8][4] = {};

    for (int k0 = 0; k0 < HH; k0 += 16) {
        float4 a0 = *reinterpret_cast<const float4*>(pAr);
        float4 a1 = *reinterpret_cast<const float4*>(pAr + 4);
        float4 a2 = *reinterpret_cast<const float4*>(pAi);
        float4 a3 = *reinterpret_cast<const float4*>(pAi + 4);
        pAr += 16; pAi += 16;
        float4 br0 = *reinterpret_cast<const float4*>(&Br[(size_t)(k0 + kb0)*HH + n0 + nb0]);
        float4 br1 = *reinterpret_cast<const float4*>(&Br[(size_t)(k0 + kb0 + 1)*HH + n0 + nb0]);
        float4 bi0 = *reinterpret_cast<const float4*>(&Bi[(size_t)(k0 + kb0)*HH + n0 + nb0]);
        float4 bi1 = *reinterpret_cast<const float4*>(&Bi[(size_t)(k0 + kb0 + 1)*HH + n0 + nb0]);

        const float ar8[8] = {a0.x,a0.y,a0.z,a0.w,a1.x,a1.y,a1.z,a1.w};
        const float ai8[8] = {a2.x,a2.y,a2.z,a2.w,a3.x,a3.y,a3.z,a3.w};
        #pragma unroll
        for (int j = 0; j < 8; j++) {
            Asr[k8 + j][rw] = ar8[j];
            Asi[k8 + j][rw] = ai8[j];
        }
        *reinterpret_cast<float4*>(&Bsr[kb0][nb0])     = br0;
        *reinterpret_cast<float4*>(&Bsr[kb0 + 1][nb0]) = br1;
        *reinterpret_cast<float4*>(&Bsi[kb0][nb0])     = bi0;
        *reinterpret_cast<float4*>(&Bsi[kb0 + 1][nb0]) = bi1;
        __syncthreads();

        #pragma unroll 2
        for (int k = 0; k < 16; k++) {
            float4 xr0 = *reinterpret_cast<const float4*>(&Asr[k][ty*8]);
            float4 xr1 = *reinterpret_cast<const float4*>(&Asr[k][ty*8+4]);
            float4 xi0 = *reinterpret_cast<const float4*>(&Asi[k][ty*8]);
            float4 xi1 = *reinterpret_cast<const float4*>(&Asi[k][ty*8+4]);
            float4 yr  = *reinterpret_cast<const float4*>(&Bsr[k][tx*4]);
            float4 yi  = *reinterpret_cast<const float4*>(&Bsi[k][tx*4]);
            const float er[8] = {xr0.x,xr0.y,xr0.z,xr0.w,xr1.x,xr1.y,xr1.z,xr1.w};
            const float ei[8] = {xi0.x,xi0.y,xi0.z,xi0.w,xi1.x,xi1.y,xi1.z,xi1.w};
            const float br[4] = {yr.x,yr.y,yr.z,yr.w};
            const float bi[4] = {yi.x,yi.y,yi.z,yi.w};
            #pragma unroll
            for (int i = 0; i < 8; i++)
                #pragma unroll
                for (int j = 0; j < 4; j++) {
                    P[i][j] += er[i] * br[j];
                    Q[i][j] += ei[i] * bi[j];
                }
        }
        __syncthreads();
    }
    const float bv = bias[z & 7];
    #pragma unroll
    for (int i = 0; i < 8; i++) {
        const int gm = m0 + ty*8 + i;   // 0..127
        float4 vp = {P[i][0]-Q[i][0] + bv, P[i][1]-Q[i][1] + bv,
                     P[i][2]-Q[i][2] + bv, P[i][3]-Q[i][3] + bv};
        *reinterpret_cast<float4*>(&O[(size_t)gm*HH + n0 + tx*4]) = vp;
        if (gm >= 2) {
            float4 vq = {P[i][0]+Q[i][0] + bv, P[i][1]+Q[i][1] + bv,
                         P[i][2]+Q[i][2] + bv, P[i][3]+Q[i][3] + bv};
            *reinterpret_cast<float4*>(&O[(size_t)(257 - gm)*HH + n0 + tx*4]) = vq;
        }
    }
}

// ---- stage 5 tail: out rows 128,129 from E5 row 128 (129 = conj partner) ----
__global__ void k_tail5(const float* __restrict__ bias, float* __restrict__ out) {
    const int z = blockIdx.x;
    const int n = threadIdx.x;
    const float* __restrict__ Br = g_T2r + (size_t)z * SQ;
    const float* __restrict__ Bi = g_T2i + (size_t)z * SQ;
    float P = 0.f, Q = 0.f;
    for (int ky = 0; ky < HH; ky++) {
        P += g_E5r[128*HH + ky] * Br[(size_t)ky*HH + n];
        Q += g_E5i[128*HH + ky] * Bi[(size_t)ky*HH + n];
    }
    const float bv = bias[z & 7];
    out[(size_t)z*SQ + 128*HH + n] = P - Q + bv;
    out[(size_t)z*SQ + 129*HH + n] = P + Q + bv;
}

extern "C" void kernel_launch(void* const* d_in, const int* in_sizes, int n_in,
                              void* d_out, int out_size) {
    (void)in_sizes; (void)n_in; (void)out_size;
    const float* im   = (const float*)d_in[0];  // [4,4,256,256]
    const float* w    = (const float*)d_in[1];  // [8,4,511,511,2]
    const float* bias = (const float*)d_in[2];  // [8,1,1]
    float* out = (float*)d_out;                 // [4,8,256,256]

    k_twiddle<<<256, 256>>>();
    k_stage1 <<<dim3(4, 4, BC), dim3(16, 16)>>>(im);   // 256x256 c, K=256
    k_stage2 <<<dim3(8, 4, BC), 128>>>();              // P,Q 256x256, K=256
    k_pointwise<<<dim3(SQ / 256, NCOUT), 256>>>(w);    // 256x256 grid
    k_stage4 <<<dim3(4, 4, BO), 128>>>();              // T2 distinct cols 0..127
    k_tail4  <<<dim3(32, BO), 256>>>();                // T2 cols 128,129
    k_stage5 <<<dim3(4, 2, BO), 128>>>(bias, out);     // out rows 0..127 + partners
    k_tail5  <<<BO, 256>>>(bias, out);                 // out rows 128,129
}

// round 10
// speedup vs baseline: 2.0190x; 1.1416x over previous
#include <cuda_runtime.h>

// FourierConv2D via DFT-as-GEMM (plain fp32 FFMA) with five symmetry folds:
//  1) real input => only ky=0..255 of the 511-row spectrum
//  2) forward col-DFT: P/Q shared-product pairs give F(kx), F(511-kx) together
//  3) inverse col-DFT K-fold: S=G+G', D=G-G' => K=256
//  4) inverse col-DFT x-fold: Ec[257-x]=conj(Ec[x]) => distinct x=0..127 (+tail 128/129)
//  5) row-inverse y-fold: E5[257-y]=conj(E5[y]) => distinct y=0..127 (+tail 128/129)
// Total ~6.4 GFLOP fp32.
// R10: all GEMM stages re-tiled to 32x32 tiles / 128 threads / 1024 blocks
// (6.9 blocks/SM -> wave-imbalance 1.16x -> 1.01x; 27 warps/SM).

namespace {
constexpr int N5    = 511;
constexpr int HH    = 256;
constexpr int NB    = 4;
constexpr int NCIN  = 4;
constexpr int NCOUT = 8;
constexpr int PLANE = N5 * N5;
constexpr int SQ    = HH * HH;       // 65536
constexpr int BC    = NB * NCIN;     // 16
constexpr int BO    = NB * NCOUT;    // 32
}

// ---- scratch (device globals) ----
__device__ float  g_Ar[SQ],  g_Ai[SQ];   // A[kx][n] = exp(-2pi i kx n/511)
__device__ float2 g_E[SQ];               // {Er,Ei}[x][kx] = exp(+2pi i kx (x+127)/511)/511
__device__ float  g_E5r[SQ], g_E5i[SQ];  // E5[y][ky] = w(ky) exp(+2pi i ky (y+127)/511)
__device__ float  g_T1r[BC*SQ], g_T1i[BC*SQ];
__device__ float2 g_P[BC*SQ], g_Q[BC*SQ];   // F(kx), F(511-kx), kx=0..255
__device__ float4 g_SD[BO*SQ];              // {Sr,Si,Dr,Di}[ky][kx]
__device__ float  g_T2r[BO*SQ], g_T2i[BO*SQ];

// ---- twiddle init ----
__global__ void k_twiddle() {
    const int idx = blockIdx.x * blockDim.x + threadIdx.x;   // 0..65535
    const float TWO_PI = 6.283185307179586f;
    const int r = idx >> 8, c = idx & 255;
    {   int m = (r * c) % N5;
        float s, co; sincosf(TWO_PI * (float)m / (float)N5, &s, &co);
        g_Ar[idx] = co;  g_Ai[idx] = -s;
    }
    {   int m = (c * (r + 127)) % N5;
        float s, co; sincosf(TWO_PI * (float)m / (float)N5, &s, &co);
        const float inv = 1.0f / (float)N5;
        g_E[idx] = make_float2(co * inv, s * inv);
    }
    {   int m = (c * (r + 127)) % N5;
        float s, co; sincosf(TWO_PI * (float)m / (float)N5, &s, &co);
        const float w = (c == 0) ? (1.0f / (float)N5) : (2.0f / (float)N5);
        g_E5r[idx] = co * w;  g_E5i[idx] = s * w;
    }
}

// All GEMM kernels: 32(m) x 32(n) tile, 128 threads, K-chunk 16.
// Compute map: ty=tid>>4 (8 groups x 4 rows), tx=tid&15 (16 groups x 2 cols).
// A-loader map: ra=tid>>2 (32 rows), ka=(tid&3)*4 (4 consecutive k).
// B-loader map (k-major source): kb=tid>>3 (16 k-rows), nb=(tid&7)*4 (4 cols).

// ---- stage 1: T1[z] (256x256 cplx) = A[0:256] (cplx) @ X[z] (256x256 real) ----
__global__ void __launch_bounds__(128) k_stage1(const float* __restrict__ im) {
    const int z = blockIdx.z;
    const float* __restrict__ X = im + (size_t)z * SQ;
    float* __restrict__ Cr = g_T1r + (size_t)z * SQ;
    float* __restrict__ Ci = g_T1i + (size_t)z * SQ;

    __shared__ float Asr[16][36], Asi[16][36], Bs[16][36];
    const int tid = threadIdx.x;
    const int tx = tid & 15, ty = tid >> 4;
    const int m0 = blockIdx.y * 32, n0 = blockIdx.x * 32;
    const int ra = tid >> 2, ka = (tid & 3) * 4;
    const int kb = tid >> 3, nb = (tid & 7) * 4;

    float cr[4][2] = {}, ci[4][2] = {};

    for (int k0 = 0; k0 < HH; k0 += 16) {
        float4 arv = *reinterpret_cast<const float4*>(g_Ar + (size_t)(m0 + ra)*HH + k0 + ka);
        float4 aiv = *reinterpret_cast<const float4*>(g_Ai + (size_t)(m0 + ra)*HH + k0 + ka);
        float4 bv  = *reinterpret_cast<const float4*>(X + (size_t)(k0 + kb)*HH + n0 + nb);
        Asr[ka+0][ra]=arv.x; Asr[ka+1][ra]=arv.y; Asr[ka+2][ra]=arv.z; Asr[ka+3][ra]=arv.w;
        Asi[ka+0][ra]=aiv.x; Asi[ka+1][ra]=aiv.y; Asi[ka+2][ra]=aiv.z; Asi[ka+3][ra]=aiv.w;
        Bs[kb][nb+0]=bv.x; Bs[kb][nb+1]=bv.y; Bs[kb][nb+2]=bv.z; Bs[kb][nb+3]=bv.w;
        __syncthreads();

        #pragma unroll 4
        for (int k = 0; k < 16; k++) {
            float4 a_r = *reinterpret_cast<const float4*>(&Asr[k][ty*4]);
            float4 a_i = *reinterpret_cast<const float4*>(&Asi[k][ty*4]);
            float2 b   = *reinterpret_cast<const float2*>(&Bs[k][tx*2]);
            const float ar[4] = {a_r.x, a_r.y, a_r.z, a_r.w};
            const float ai[4] = {a_i.x, a_i.y, a_i.z, a_i.w};
            const float bb[2] = {b.x, b.y};
            #pragma unroll
            for (int i = 0; i < 4; i++)
                #pragma unroll
                for (int j = 0; j < 2; j++) {
                    cr[i][j] += ar[i] * bb[j];
                    ci[i][j] += ai[i] * bb[j];
                }
        }
        __syncthreads();
    }
    const int gn = n0 + tx*2;
    #pragma unroll
    for (int i = 0; i < 4; i++) {
        const int gm = m0 + ty*4 + i;
        *reinterpret_cast<float2*>(Cr + (size_t)gm*HH + gn) = make_float2(cr[i][0], cr[i][1]);
        *reinterpret_cast<float2*>(Ci + (size_t)gm*HH + gn) = make_float2(ci[i][0], ci[i][1]);
    }
}

// ---- stage 2: P,Q[z][ky][kx] via shared products U/V/X/Y ----
// P = (U-V, X+Y) = F(kx);  Q = (U+V, Y-X) = F(511-kx)
__global__ void __launch_bounds__(128) k_stage2() {
    const int z = blockIdx.z;
    const float* __restrict__ T1r = g_T1r + (size_t)z * SQ;
    const float* __restrict__ T1i = g_T1i + (size_t)z * SQ;
    float2* __restrict__ P = g_P + (size_t)z * SQ;
    float2* __restrict__ Q = g_Q + (size_t)z * SQ;

    __shared__ float Asr[16][36], Asi[16][36], Bsr[16][36], Bsi[16][36];
    const int tid = threadIdx.x;
    const int tx = tid & 15, ty = tid >> 4;
    const int m0 = blockIdx.y * 32, n0 = blockIdx.x * 32;
    const int ra = tid >> 2, ka = (tid & 3) * 4;

    float U[4][2] = {}, V[4][2] = {}, Xc[4][2] = {}, Yc[4][2] = {};

    for (int k0 = 0; k0 < HH; k0 += 16) {
        float4 arv = *reinterpret_cast<const float4*>(T1r + (size_t)(m0 + ra)*HH + k0 + ka);
        float4 aiv = *reinterpret_cast<const float4*>(T1i + (size_t)(m0 + ra)*HH + k0 + ka);
        float4 brv = *reinterpret_cast<const float4*>(g_Ar + (size_t)(n0 + ra)*HH + k0 + ka);
        float4 biv = *reinterpret_cast<const float4*>(g_Ai + (size_t)(n0 + ra)*HH + k0 + ka);
        Asr[ka+0][ra]=arv.x; Asr[ka+1][ra]=arv.y; Asr[ka+2][ra]=arv.z; Asr[ka+3][ra]=arv.w;
        Asi[ka+0][ra]=aiv.x; Asi[ka+1][ra]=aiv.y; Asi[ka+2][ra]=aiv.z; Asi[ka+3][ra]=aiv.w;
        Bsr[ka+0][ra]=brv.x; Bsr[ka+1][ra]=brv.y; Bsr[ka+2][ra]=brv.z; Bsr[ka+3][ra]=brv.w;
        Bsi[ka+0][ra]=biv.x; Bsi[ka+1][ra]=biv.y; Bsi[ka+2][ra]=biv.z; Bsi[ka+3][ra]=biv.w;
        __syncthreads();

        #pragma unroll 4
        for (int k = 0; k < 16; k++) {
            float4 a_r = *reinterpret_cast<const float4*>(&Asr[k][ty*4]);
            float4 a_i = *reinterpret_cast<const float4*>(&Asi[k][ty*4]);
            float2 b_r = *reinterpret_cast<const float2*>(&Bsr[k][tx*2]);
            float2 b_i = *reinterpret_cast<const float2*>(&Bsi[k][tx*2]);
            const float ar[4] = {a_r.x, a_r.y, a_r.z, a_r.w};
            const float ai[4] = {a_i.x, a_i.y, a_i.z, a_i.w};
            const float wr[2] = {b_r.x, b_r.y};
            const float wi[2] = {b_i.x, b_i.y};
            #pragma unroll
            for (int i = 0; i < 4; i++)
                #pragma unroll
                for (int j = 0; j < 2; j++) {
                    U [i][j] += ar[i] * wr[j];
                    V [i][j] += ai[i] * wi[j];
                    Xc[i][j] += ar[i] * wi[j];
                    Yc[i][j] += ai[i] * wr[j];
                }
        }
        __syncthreads();
    }
    const int gn = n0 + tx*2;
    #pragma unroll
    for (int i = 0; i < 4; i++) {
        const int gm = m0 + ty*4 + i;
        float4 pv = make_float4(U[i][0]-V[i][0], Xc[i][0]+Yc[i][0],
                                U[i][1]-V[i][1], Xc[i][1]+Yc[i][1]);
        float4 qv = make_float4(U[i][0]+V[i][0], Yc[i][0]-Xc[i][0],
                                U[i][1]+V[i][1], Yc[i][1]-Xc[i][1]);
        *reinterpret_cast<float4*>(P + (size_t)gm*HH + gn) = pv;
        *reinterpret_cast<float4*>(Q + (size_t)gm*HH + gn) = qv;
    }
}

// ---- stage 3: pointwise Hermitian-W multiply + cin sum + S/D combine ----
__global__ void k_pointwise(const float* __restrict__ w) {
    const int p = blockIdx.x * blockDim.x + threadIdx.x;  // ky*256+kx
    const int o = blockIdx.y;
    const int ky = p >> 8, kx = p & 255;
    const int ky2 = (N5 - ky) % N5;
    const int kx2 = (N5 - kx) % N5;

    float2 wh1[NCIN], wh2[NCIN];
    #pragma unroll
    for (int c = 0; c < NCIN; c++) {
        const float* wb = w + (size_t)(o*NCIN + c) * PLANE * 2;
        const float2 a = *reinterpret_cast<const float2*>(wb + ((size_t)ky *N5 + kx )*2);
        const float2 bq= *reinterpret_cast<const float2*>(wb + ((size_t)ky2*N5 + kx2)*2);
        wh1[c] = make_float2(0.5f*(a.x + bq.x), 0.5f*(a.y - bq.y));
        if (kx != 0) {
            const float2 e = *reinterpret_cast<const float2*>(wb + ((size_t)ky *N5 + (N5-kx))*2);
            const float2 f = *reinterpret_cast<const float2*>(wb + ((size_t)ky2*N5 + kx     )*2);
            wh2[c] = make_float2(0.5f*(e.x + f.x), 0.5f*(e.y - f.y));
        } else {
            wh2[c] = make_float2(0.f, 0.f);
        }
    }
    #pragma unroll
    for (int b = 0; b < NB; b++) {
        float gr = 0.f, gi = 0.f, hr = 0.f, hi = 0.f;
        #pragma unroll
        for (int c = 0; c < NCIN; c++) {
            const float2 Pv = g_P[(size_t)(b*NCIN + c)*SQ + p];
            const float2 Qv = g_Q[(size_t)(b*NCIN + c)*SQ + p];
            gr += Pv.x * wh1[c].x - Pv.y * wh1[c].y;
            gi += Pv.x * wh1[c].y + Pv.y * wh1[c].x;
            hr += Qv.x * wh2[c].x - Qv.y * wh2[c].y;
            hi += Qv.x * wh2[c].y + Qv.y * wh2[c].x;
        }
        g_SD[(size_t)(b*NCOUT + o)*SQ + p] =
            make_float4(gr + hr, gi + hi, gr - hr, gi - hi);
    }
}

// ---- stage 4 (x-folded): distinct cols t=0..127, partners x=257-t (t>=2) ----
// P=Sum Sr*Er, Q=Sum Di*Ei, R=Sum Si*Er, T=Sum Dr*Ei  over kx
// T2[ky][t] = (P-Q, R+T);  T2[ky][257-t] = (P+Q, R-T)
__global__ void __launch_bounds__(128) k_stage4() {
    const int z = blockIdx.z;
    const float4* __restrict__ Ag = g_SD + (size_t)z * SQ;
    float* __restrict__ Cr = g_T2r + (size_t)z * SQ;
    float* __restrict__ Ci = g_T2i + (size_t)z * SQ;

    __shared__ float4 As4[16][33];    // [k][ky-row]; float4 elements -> 16B aligned
    __shared__ float2 Bs2[16][34];    // [k][col t]; row 272B = 17*16 (float4-read safe)
    const int tid = threadIdx.x;
    const int tx = tid & 15, ty = tid >> 4;
    const int m0 = blockIdx.y * 32, n0 = blockIdx.x * 32;
    const int ra = tid >> 2, ka = (tid & 3) * 4;

    float P[4][2] = {}, Q[4][2] = {}, R[4][2] = {}, T[4][2] = {};

    for (int k0 = 0; k0 < HH; k0 += 16) {
        #pragma unroll
        for (int j = 0; j < 4; j++)
            As4[ka + j][ra] = Ag[(size_t)(m0 + ra)*HH + k0 + ka + j];
        {   const float4* src = reinterpret_cast<const float4*>(g_E + (size_t)(n0 + ra)*HH + k0 + ka);
            float4 e01 = src[0], e23 = src[1];
            Bs2[ka+0][ra] = make_float2(e01.x, e01.y);
            Bs2[ka+1][ra] = make_float2(e01.z, e01.w);
            Bs2[ka+2][ra] = make_float2(e23.x, e23.y);
            Bs2[ka+3][ra] = make_float2(e23.z, e23.w);
        }
        __syncthreads();

        #pragma unroll 2
        for (int k = 0; k < 16; k++) {
            float4 a[4];
            #pragma unroll
            for (int i = 0; i < 4; i++) a[i] = As4[k][ty*4 + i];
            float4 bvec = *reinterpret_cast<const float4*>(&Bs2[k][tx*2]);  // {Er0,Ei0,Er1,Ei1}
            const float er[2] = {bvec.x, bvec.z};
            const float ei[2] = {bvec.y, bvec.w};
            #pragma unroll
            for (int i = 0; i < 4; i++)
                #pragma unroll
                for (int j = 0; j < 2; j++) {
                    P[i][j] += a[i].x * er[j];   // Sr*Er
                    Q[i][j] += a[i].w * ei[j];   // Di*Ei
                    R[i][j] += a[i].y * er[j];   // Si*Er
                    T[i][j] += a[i].z * ei[j];   // Dr*Ei
                }
        }
        __syncthreads();
    }
    const int t0 = n0 + tx*2;
    #pragma unroll
    for (int i = 0; i < 4; i++) {
        const int gm = m0 + ty*4 + i;
        *reinterpret_cast<float2*>(Cr + (size_t)gm*HH + t0) =
            make_float2(P[i][0]-Q[i][0], P[i][1]-Q[i][1]);
        *reinterpret_cast<float2*>(Ci + (size_t)gm*HH + t0) =
            make_float2(R[i][0]+T[i][0], R[i][1]+T[i][1]);
        if (t0 >= 2) {
            *reinterpret_cast<float2*>(Cr + (size_t)gm*HH + 256 - t0) =
                make_float2(P[i][1]+Q[i][1], P[i][0]+Q[i][0]);
            *reinterpret_cast<float2*>(Ci + (size_t)gm*HH + 256 - t0) =
                make_float2(R[i][1]-T[i][1], R[i][0]-T[i][0]);
        }
    }
}

// ---- stage 4 tail: T2 cols 128,129 from E row 128 (129 = conj partner) ----
__global__ void k_tail4() {
    const int z = blockIdx.y;
    const int warp = threadIdx.x >> 5, lane = threadIdx.x & 31;
    const int ky = blockIdx.x * 8 + warp;
    const float4* __restrict__ Arow = g_SD + (size_t)z * SQ + (size_t)ky * HH;
    float P = 0.f, Q = 0.f, R = 0.f, T = 0.f;
    for (int kx = lane; kx < HH; kx += 32) {
        const float4 a = Arow[kx];
        const float2 e = g_E[128*HH + kx];
        P += a.x * e.x;  Q += a.w * e.y;
        R += a.y * e.x;  T += a.z * e.y;
    }
    #pragma unroll
    for (int off = 16; off; off >>= 1) {
        P += __shfl_down_sync(0xffffffffu, P, off);
        Q += __shfl_down_sync(0xffffffffu, Q, off);
        R += __shfl_down_sync(0xffffffffu, R, off);
        T += __shfl_down_sync(0xffffffffu, T, off);
    }
    if (lane == 0) {
        float* Cr = g_T2r + (size_t)z * SQ + (size_t)ky * HH;
        float* Ci = g_T2i + (size_t)z * SQ + (size_t)ky * HH;
        Cr[128] = P - Q;  Ci[128] = R + T;
        Cr[129] = P + Q;  Ci[129] = R - T;
    }
}

// ---- stage 5 (y-folded): distinct rows y=0..127, partners 257-y (y>=2) ----
// P=Sum E5r*T2r, Q=Sum E5i*T2i;  out[y]=P-Q+b;  out[257-y]=P+Q+b
__global__ void __launch_bounds__(128) k_stage5(const float* __restrict__ bias,
                                                float* __restrict__ out) {
    const int z = blockIdx.z;
    const float* __restrict__ Br = g_T2r + (size_t)z * SQ;
    const float* __restrict__ Bi = g_T2i + (size_t)z * SQ;
    float* __restrict__ O = out + (size_t)z * SQ;

    __shared__ float Asr[16][36], Asi[16][36], Bsr[16][36], Bsi[16][36];
    const int tid = threadIdx.x;
    const int tx = tid & 15, ty = tid >> 4;
    const int m0 = blockIdx.y * 32, n0 = blockIdx.x * 32;  // m0 in {0,32,64,96}
    const int ra = tid >> 2, ka = (tid & 3) * 4;
    const int kb = tid >> 3, nb = (tid & 7) * 4;

    float P[4][2] = {}, Q[4][2] = {};

    for (int k0 = 0; k0 < HH; k0 += 16) {
        float4 arv = *reinterpret_cast<const float4*>(g_E5r + (size_t)(m0 + ra)*HH + k0 + ka);
        float4 aiv = *reinterpret_cast<const float4*>(g_E5i + (size_t)(m0 + ra)*HH + k0 + ka);
        float4 brv = *reinterpret_cast<const float4*>(Br + (size_t)(k0 + kb)*HH + n0 + nb);
        float4 biv = *reinterpret_cast<const float4*>(Bi + (size_t)(k0 + kb)*HH + n0 + nb);
        Asr[ka+0][ra]=arv.x; Asr[ka+1][ra]=arv.y; Asr[ka+2][ra]=arv.z; Asr[ka+3][ra]=arv.w;
        Asi[ka+0][ra]=aiv.x; Asi[ka+1][ra]=aiv.y; Asi[ka+2][ra]=aiv.z; Asi[ka+3][ra]=aiv.w;
        Bsr[kb][nb+0]=brv.x; Bsr[kb][nb+1]=brv.y; Bsr[kb][nb+2]=brv.z; Bsr[kb][nb+3]=brv.w;
        Bsi[kb][nb+0]=biv.x; Bsi[kb][nb+1]=biv.y; Bsi[kb][nb+2]=biv.z; Bsi[kb][nb+3]=biv.w;
        __syncthreads();

        #pragma unroll 4
        for (int k = 0; k < 16; k++) {
            float4 e_r = *reinterpret_cast<const float4*>(&Asr[k][ty*4]);
            float4 e_i = *reinterpret_cast<const float4*>(&Asi[k][ty*4]);
            float2 b_r = *reinterpret_cast<const float2*>(&Bsr[k][tx*2]);
            float2 b_i = *reinterpret_cast<const float2*>(&Bsi[k][tx*2]);
            const float er[4] = {e_r.x, e_r.y, e_r.z, e_r.w};
            const float ei[4] = {e_i.x, e_i.y, e_i.z, e_i.w};
            const float br[2] = {b_r.x, b_r.y};
            const float bi[2] = {b_i.x, b_i.y};
            #pragma unroll
            for (int i = 0; i < 4; i++)
                #pragma unroll
                for (int j = 0; j < 2; j++) {
                    P[i][j] += er[i] * br[j];
                    Q[i][j] += ei[i] * bi[j];
                }
        }
        __syncthreads();
    }
    const float bv = bias[z & 7];
    const int gn = n0 + tx*2;
    #pragma unroll
    for (int i = 0; i < 4; i++) {
        const int gm = m0 + ty*4 + i;   // 0..127
        *reinterpret_cast<float2*>(&O[(size_t)gm*HH + gn]) =
            make_float2(P[i][0]-Q[i][0] + bv, P[i][1]-Q[i][1] + bv);
        if (gm >= 2) {
            *reinterpret_cast<float2*>(&O[(size_t)(257 - gm)*HH + gn]) =
                make_float2(P[i][0]+Q[i][0] + bv, P[i][1]+Q[i][1] + bv);
        }
    }
}

// ---- stage 5 tail: out rows 128,129 from E5 row 128 (129 = conj partner) ----
__global__ void k_tail5(const float* __restrict__ bias, float* __restrict__ out) {
    const int z = blockIdx.x;
    const int n = threadIdx.x;
    const float* __restrict__ Br = g_T2r + (size_t)z * SQ;
    const float* __restrict__ Bi = g_T2i + (size_t)z * SQ;
    float P = 0.f, Q = 0.f;
    for (int ky = 0; ky < HH; ky++) {
        P += g_E5r[128*HH + ky] * Br[(size_t)ky*HH + n];
        Q += g_E5i[128*HH + ky] * Bi[(size_t)ky*HH + n];
    }
    const float bv = bias[z & 7];
    out[(size_t)z*SQ + 128*HH + n] = P - Q + bv;
    out[(size_t)z*SQ + 129*HH + n] = P + Q + bv;
}

extern "C" void kernel_launch(void* const* d_in, const int* in_sizes, int n_in,
                              void* d_out, int out_size) {
    (void)in_sizes; (void)n_in; (void)out_size;
    const float* im   = (const float*)d_in[0];  // [4,4,256,256]
    const float* w    = (const float*)d_in[1];  // [8,4,511,511,2]
    const float* bias = (const float*)d_in[2];  // [8,1,1]
    float* out = (float*)d_out;                 // [4,8,256,256]

    k_twiddle<<<256, 256>>>();
    k_stage1 <<<dim3(8, 8, BC), 128>>>(im);            // 1024 blocks
    k_stage2 <<<dim3(8, 8, BC), 128>>>();              // 1024 blocks
    k_pointwise<<<dim3(SQ / 256, NCOUT), 256>>>(w);
    k_stage4 <<<dim3(4, 8, BO), 128>>>();              // 1024 blocks, t 0..127
    k_tail4  <<<dim3(32, BO), 256>>>();                // T2 cols 128,129
    k_stage5 <<<dim3(8, 4, BO), 128>>>(bias, out);     // 1024 blocks, y 0..127
    k_tail5  <<<BO, 256>>>(bias, out);                 // out rows 128,129
}